// round 1
// baseline (speedup 1.0000x reference)
#include <cuda_runtime.h>
#include <math.h>

#define N_NODES 100000
#define F_IN    128
#define H_DIM   16
#define C_DIM   40

// ---- scratch (device globals: no allocation allowed) ----
__device__ float g_y   [N_NODES * H_DIM];   // x @ W1[1]
__device__ float g_r1  [N_NODES * H_DIM];   // x @ root1
__device__ float g_deg [N_NODES];
__device__ float g_acc1[N_NODES * H_DIM];
__device__ float g_h   [N_NODES * H_DIM];   // elu(layer1)
__device__ float g_acc2[N_NODES * H_DIM];

// ---------------------------------------------------------------------------
// zero accumulators + degree
__global__ void k_zero() {
    int i = blockIdx.x * blockDim.x + threadIdx.x;
    if (i < N_NODES * H_DIM) { g_acc1[i] = 0.f; g_acc2[i] = 0.f; }
    if (i < N_NODES) g_deg[i] = 0.f;
}

// ---------------------------------------------------------------------------
// proj1: y = x @ W1[1]  (cols 0..15)  and  r1 = x @ root1 (cols 16..31)
// M=100000, N=32, K=128. Tile: 64 nodes/block, 256 threads.
// Warp w handles nodes [w*8, w*8+8), lane = output column.
// x staged in SMEM in two K-chunks of 64; all x reads are warp-broadcast
// (lanes differ only in column), so no bank conflicts regardless of stride.
__global__ __launch_bounds__(256) void k_proj1(const float* __restrict__ x,
                                               const float* __restrict__ W1,
                                               const float* __restrict__ root1) {
    __shared__ float sW[F_IN * 32];   // 16 KB, [k][c]
    __shared__ float sx[64 * 64];     // 16 KB, [node][k_local]

    const int tid  = threadIdx.x;
    const int lane = tid & 31;
    const int w    = tid >> 5;
    const int base = blockIdx.x * 64;

    const float* W1k = W1 + F_IN * H_DIM;  // kernel index 1
    for (int i = tid; i < F_IN * 32; i += 256) {
        int k = i >> 5, c = i & 31;
        sW[i] = (c < 16) ? W1k[k * 16 + c] : root1[k * 16 + (c - 16)];
    }

    float acc[8];
#pragma unroll
    for (int m = 0; m < 8; m++) acc[m] = 0.f;

    const float4* x4 = (const float4*)x;
    for (int kc = 0; kc < 2; kc++) {
        __syncthreads();
        // stage 64 nodes x 64 k-values (coalesced float4)
        for (int i = tid; i < 64 * 16; i += 256) {
            int node = i >> 4, k4 = i & 15;
            int ng = base + node;
            float4 v = make_float4(0.f, 0.f, 0.f, 0.f);
            if (ng < N_NODES) v = x4[ng * 32 + kc * 16 + k4];
            *(float4*)&sx[node * 64 + k4 * 4] = v;
        }
        __syncthreads();

#pragma unroll
        for (int kl = 0; kl < 64; kl += 4) {
            int kg = kc * 64 + kl;
            float w0 = sW[(kg + 0) * 32 + lane];
            float w1 = sW[(kg + 1) * 32 + lane];
            float w2 = sW[(kg + 2) * 32 + lane];
            float w3 = sW[(kg + 3) * 32 + lane];
#pragma unroll
            for (int m = 0; m < 8; m++) {
                float4 xv = *(const float4*)&sx[(w * 8 + m) * 64 + kl];
                acc[m] = fmaf(xv.x, w0, acc[m]);
                acc[m] = fmaf(xv.y, w1, acc[m]);
                acc[m] = fmaf(xv.z, w2, acc[m]);
                acc[m] = fmaf(xv.w, w3, acc[m]);
            }
        }
    }

#pragma unroll
    for (int m = 0; m < 8; m++) {
        int ng = base + w * 8 + m;
        if (ng < N_NODES) {
            if (lane < 16) g_y [ng * 16 + lane]        = acc[m];
            else           g_r1[ng * 16 + (lane - 16)] = acc[m];
        }
    }
}

// ---------------------------------------------------------------------------
// edge pass: gather 16-dim feature of src, scatter-add into acc[dst].
// layer 0: feat = g_y, acc = g_acc1, also counts degree.
// layer 1: feat = g_h, acc = g_acc2.
__global__ __launch_bounds__(256) void k_edge(const int* __restrict__ src,
                                              const int* __restrict__ dst,
                                              int E, int layer) {
    int e = blockIdx.x * blockDim.x + threadIdx.x;
    if (e >= E) return;
    int s = src[e];
    int d = dst[e];
    const float* feat = (layer == 0) ? g_y : g_h;
    float*       acc  = (layer == 0) ? g_acc1 : g_acc2;

    const float4* fp = (const float4*)(feat + (size_t)s * 16);
    float4 v0 = fp[0], v1 = fp[1], v2 = fp[2], v3 = fp[3];
    float4* ap = (float4*)(acc + (size_t)d * 16);
    atomicAdd(ap + 0, v0);
    atomicAdd(ap + 1, v1);
    atomicAdd(ap + 2, v2);
    atomicAdd(ap + 3, v3);
    if (layer == 0) atomicAdd(&g_deg[d], 1.0f);
}

// ---------------------------------------------------------------------------
// combine1: h = elu(acc1/clip(deg,1) + r1 + b1), vectorized float4 (4 per node-row chunk)
__global__ void k_combine1(const float* __restrict__ b1) {
    int i = blockIdx.x * blockDim.x + threadIdx.x;  // float4 index over N*4
    if (i >= N_NODES * 4) return;
    int n  = i >> 2;
    int cb = (i & 3) * 4;
    float inv = 1.0f / fmaxf(g_deg[n], 1.0f);
    float4 a = *(const float4*)&g_acc1[i * 4];
    float4 r = *(const float4*)&g_r1[i * 4];
    float v0 = a.x * inv + r.x + b1[cb + 0];
    float v1 = a.y * inv + r.y + b1[cb + 1];
    float v2 = a.z * inv + r.z + b1[cb + 2];
    float v3 = a.w * inv + r.w + b1[cb + 3];
    float4 o;
    o.x = (v0 > 0.f) ? v0 : expm1f(v0);
    o.y = (v1 > 0.f) ? v1 : expm1f(v1);
    o.z = (v2 > 0.f) ? v2 : expm1f(v2);
    o.w = (v3 > 0.f) ? v3 : expm1f(v3);
    *(float4*)&g_h[i * 4] = o;
}

// ---------------------------------------------------------------------------
// out: logits = (acc2/clip(deg,1)) @ W2[1] + h @ root2 + b2 ; log_softmax(40)
// One warp per node. Lanes 0..15 hold scaled acc2 row, lanes 16..31 hold h row.
__global__ __launch_bounds__(256) void k_out(const float* __restrict__ W2,
                                             const float* __restrict__ root2,
                                             const float* __restrict__ b2,
                                             float* __restrict__ out) {
    __shared__ float sA[H_DIM * C_DIM];  // W2[1]
    __shared__ float sR[H_DIM * C_DIM];  // root2
    __shared__ float sB[C_DIM];

    const int tid = threadIdx.x;
    const float* W2k = W2 + H_DIM * C_DIM;
    for (int i = tid; i < H_DIM * C_DIM; i += 256) { sA[i] = W2k[i]; sR[i] = root2[i]; }
    if (tid < C_DIM) sB[tid] = b2[tid];
    __syncthreads();

    const int lane = tid & 31;
    const int n = blockIdx.x * 8 + (tid >> 5);
    if (n >= N_NODES) return;

    float inv = 1.0f / fmaxf(g_deg[n], 1.0f);
    float regval;
    if (lane < 16) regval = g_acc2[(size_t)n * 16 + lane] * inv;
    else           regval = g_h  [(size_t)n * 16 + (lane - 16)];

    float acc0 = sB[lane];
    float acc1 = (lane < 8) ? sB[32 + lane] : 0.f;
#pragma unroll
    for (int k = 0; k < 16; k++) {
        float av = __shfl_sync(0xffffffffu, regval, k);
        float hv = __shfl_sync(0xffffffffu, regval, k + 16);
        acc0 = fmaf(av, sA[k * 40 + lane], acc0);
        acc0 = fmaf(hv, sR[k * 40 + lane], acc0);
        if (lane < 8) {
            acc1 = fmaf(av, sA[k * 40 + 32 + lane], acc1);
            acc1 = fmaf(hv, sR[k * 40 + 32 + lane], acc1);
        }
    }

    // log_softmax over 40 columns
    float lm = acc0;
    if (lane < 8) lm = fmaxf(lm, acc1);
#pragma unroll
    for (int off = 16; off > 0; off >>= 1)
        lm = fmaxf(lm, __shfl_xor_sync(0xffffffffu, lm, off));
    float se = __expf(acc0 - lm) + ((lane < 8) ? __expf(acc1 - lm) : 0.f);
#pragma unroll
    for (int off = 16; off > 0; off >>= 1)
        se += __shfl_xor_sync(0xffffffffu, se, off);
    float lse = lm + __logf(se);

    out[(size_t)n * 40 + lane] = acc0 - lse;
    if (lane < 8) out[(size_t)n * 40 + 32 + lane] = acc1 - lse;
}

// ---------------------------------------------------------------------------
extern "C" void kernel_launch(void* const* d_in, const int* in_sizes, int n_in,
                              void* d_out, int out_size) {
    const float* x     = (const float*)d_in[0];
    const int*   ei    = (const int*)  d_in[1];
    const float* W1    = (const float*)d_in[2];
    const float* root1 = (const float*)d_in[3];
    const float* b1    = (const float*)d_in[4];
    const float* W2    = (const float*)d_in[5];
    const float* root2 = (const float*)d_in[6];
    const float* b2    = (const float*)d_in[7];
    float* out = (float*)d_out;

    const int E = in_sizes[1] / 2;
    const int* src = ei;
    const int* dst = ei + E;

    k_zero<<<(N_NODES * H_DIM + 255) / 256, 256>>>();
    k_proj1<<<(N_NODES + 63) / 64, 256>>>(x, W1, root1);
    k_edge<<<(E + 255) / 256, 256>>>(src, dst, E, 0);
    k_combine1<<<(N_NODES * 4 + 255) / 256, 256>>>(b1);
    k_edge<<<(E + 255) / 256, 256>>>(src, dst, E, 1);
    k_out<<<(N_NODES + 7) / 8, 256>>>(W2, root2, b2, out);
}

// round 2
// speedup vs baseline: 1.3185x; 1.3185x over previous
#include <cuda_runtime.h>
#include <math.h>

#define N_NODES 100000
#define F_IN    128
#define H_DIM   16
#define C_DIM   40

// ---- scratch (device globals: no allocation allowed) ----
__device__ float g_y   [N_NODES * H_DIM];   // x @ W1[1]
__device__ float g_r1  [N_NODES * H_DIM];   // x @ root1
__device__ float g_deg [N_NODES];
__device__ float g_acc1[N_NODES * H_DIM];
__device__ float g_h   [N_NODES * H_DIM];   // elu(layer1)
__device__ float g_acc2[N_NODES * H_DIM];

// ---------------------------------------------------------------------------
// zero accumulators + degree
__global__ void k_zero() {
    int i = blockIdx.x * blockDim.x + threadIdx.x;
    if (i < N_NODES * H_DIM) { g_acc1[i] = 0.f; g_acc2[i] = 0.f; }
    if (i < N_NODES) g_deg[i] = 0.f;
}

// ---------------------------------------------------------------------------
// proj1: y = x @ W1[1]  (cols 0..15)  and  r1 = x @ root1 (cols 16..31)
// M=100000, N=32, K=128. Tile: 64 nodes/block, 256 threads.
__global__ __launch_bounds__(256) void k_proj1(const float* __restrict__ x,
                                               const float* __restrict__ W1,
                                               const float* __restrict__ root1) {
    __shared__ float sW[F_IN * 32];   // 16 KB, [k][c]
    __shared__ float sx[64 * 64];     // 16 KB, [node][k_local]

    const int tid  = threadIdx.x;
    const int lane = tid & 31;
    const int w    = tid >> 5;
    const int base = blockIdx.x * 64;

    const float* W1k = W1 + F_IN * H_DIM;  // kernel index 1
    for (int i = tid; i < F_IN * 32; i += 256) {
        int k = i >> 5, c = i & 31;
        sW[i] = (c < 16) ? W1k[k * 16 + c] : root1[k * 16 + (c - 16)];
    }

    float acc[8];
#pragma unroll
    for (int m = 0; m < 8; m++) acc[m] = 0.f;

    const float4* x4 = (const float4*)x;
    for (int kc = 0; kc < 2; kc++) {
        __syncthreads();
        for (int i = tid; i < 64 * 16; i += 256) {
            int node = i >> 4, k4 = i & 15;
            int ng = base + node;
            float4 v = make_float4(0.f, 0.f, 0.f, 0.f);
            if (ng < N_NODES) v = x4[ng * 32 + kc * 16 + k4];
            *(float4*)&sx[node * 64 + k4 * 4] = v;
        }
        __syncthreads();

#pragma unroll
        for (int kl = 0; kl < 64; kl += 4) {
            int kg = kc * 64 + kl;
            float w0 = sW[(kg + 0) * 32 + lane];
            float w1 = sW[(kg + 1) * 32 + lane];
            float w2 = sW[(kg + 2) * 32 + lane];
            float w3 = sW[(kg + 3) * 32 + lane];
#pragma unroll
            for (int m = 0; m < 8; m++) {
                float4 xv = *(const float4*)&sx[(w * 8 + m) * 64 + kl];
                acc[m] = fmaf(xv.x, w0, acc[m]);
                acc[m] = fmaf(xv.y, w1, acc[m]);
                acc[m] = fmaf(xv.z, w2, acc[m]);
                acc[m] = fmaf(xv.w, w3, acc[m]);
            }
        }
    }

#pragma unroll
    for (int m = 0; m < 8; m++) {
        int ng = base + w * 8 + m;
        if (ng < N_NODES) {
            if (lane < 16) g_y [ng * 16 + lane]        = acc[m];
            else           g_r1[ng * 16 + (lane - 16)] = acc[m];
        }
    }
}

// ---------------------------------------------------------------------------
// edge pass, 4 threads per edge: thread (e, c) gathers float4 chunk c of src
// row and REDs it into chunk c of dst row. 4 consecutive lanes cover one 64B
// node row -> gather and RED coalesce within a 128B line (~1-2 wavefronts per
// edge instead of ~8 with the 1-thread-per-edge layout).
__global__ __launch_bounds__(256) void k_edge(const int* __restrict__ src,
                                              const int* __restrict__ dst,
                                              int E, int layer) {
    int t = blockIdx.x * blockDim.x + threadIdx.x;
    int e = t >> 2;
    int c = t & 3;
    if (e >= E) return;
    int s = src[e];
    int d = dst[e];

    const float4* feat = (const float4*)((layer == 0) ? g_y : g_h);
    float4*       acc  = (float4*)((layer == 0) ? g_acc1 : g_acc2);

    float4 v = feat[(size_t)s * 4 + c];
    atomicAdd(&acc[(size_t)d * 4 + c], v);
    if (layer == 0 && c == 0) atomicAdd(&g_deg[d], 1.0f);
}

// ---------------------------------------------------------------------------
// combine1: h = elu(acc1/clip(deg,1) + r1 + b1)
__global__ void k_combine1(const float* __restrict__ b1) {
    int i = blockIdx.x * blockDim.x + threadIdx.x;  // float4 index over N*4
    if (i >= N_NODES * 4) return;
    int n  = i >> 2;
    int cb = (i & 3) * 4;
    float inv = 1.0f / fmaxf(g_deg[n], 1.0f);
    float4 a = *(const float4*)&g_acc1[i * 4];
    float4 r = *(const float4*)&g_r1[i * 4];
    float v0 = a.x * inv + r.x + b1[cb + 0];
    float v1 = a.y * inv + r.y + b1[cb + 1];
    float v2 = a.z * inv + r.z + b1[cb + 2];
    float v3 = a.w * inv + r.w + b1[cb + 3];
    float4 o;
    o.x = (v0 > 0.f) ? v0 : expm1f(v0);
    o.y = (v1 > 0.f) ? v1 : expm1f(v1);
    o.z = (v2 > 0.f) ? v2 : expm1f(v2);
    o.w = (v3 > 0.f) ? v3 : expm1f(v3);
    *(float4*)&g_h[i * 4] = o;
}

// ---------------------------------------------------------------------------
// out: logits = (acc2/clip(deg,1)) @ W2[1] + h @ root2 + b2 ; log_softmax(40)
__global__ __launch_bounds__(256) void k_out(const float* __restrict__ W2,
                                             const float* __restrict__ root2,
                                             const float* __restrict__ b2,
                                             float* __restrict__ out) {
    __shared__ float sA[H_DIM * C_DIM];  // W2[1]
    __shared__ float sR[H_DIM * C_DIM];  // root2
    __shared__ float sB[C_DIM];

    const int tid = threadIdx.x;
    const float* W2k = W2 + H_DIM * C_DIM;
    for (int i = tid; i < H_DIM * C_DIM; i += 256) { sA[i] = W2k[i]; sR[i] = root2[i]; }
    if (tid < C_DIM) sB[tid] = b2[tid];
    __syncthreads();

    const int lane = tid & 31;
    const int n = blockIdx.x * 8 + (tid >> 5);
    if (n >= N_NODES) return;

    float inv = 1.0f / fmaxf(g_deg[n], 1.0f);
    float regval;
    if (lane < 16) regval = g_acc2[(size_t)n * 16 + lane] * inv;
    else           regval = g_h  [(size_t)n * 16 + (lane - 16)];

    float acc0 = sB[lane];
    float acc1 = (lane < 8) ? sB[32 + lane] : 0.f;
#pragma unroll
    for (int k = 0; k < 16; k++) {
        float av = __shfl_sync(0xffffffffu, regval, k);
        float hv = __shfl_sync(0xffffffffu, regval, k + 16);
        acc0 = fmaf(av, sA[k * 40 + lane], acc0);
        acc0 = fmaf(hv, sR[k * 40 + lane], acc0);
        if (lane < 8) {
            acc1 = fmaf(av, sA[k * 40 + 32 + lane], acc1);
            acc1 = fmaf(hv, sR[k * 40 + 32 + lane], acc1);
        }
    }

    // log_softmax over 40 columns
    float lm = acc0;
    if (lane < 8) lm = fmaxf(lm, acc1);
#pragma unroll
    for (int off = 16; off > 0; off >>= 1)
        lm = fmaxf(lm, __shfl_xor_sync(0xffffffffu, lm, off));
    float se = __expf(acc0 - lm) + ((lane < 8) ? __expf(acc1 - lm) : 0.f);
#pragma unroll
    for (int off = 16; off > 0; off >>= 1)
        se += __shfl_xor_sync(0xffffffffu, se, off);
    float lse = lm + __logf(se);

    out[(size_t)n * 40 + lane] = acc0 - lse;
    if (lane < 8) out[(size_t)n * 40 + 32 + lane] = acc1 - lse;
}

// ---------------------------------------------------------------------------
extern "C" void kernel_launch(void* const* d_in, const int* in_sizes, int n_in,
                              void* d_out, int out_size) {
    const float* x     = (const float*)d_in[0];
    const int*   ei    = (const int*)  d_in[1];
    const float* W1    = (const float*)d_in[2];
    const float* root1 = (const float*)d_in[3];
    const float* b1    = (const float*)d_in[4];
    const float* W2    = (const float*)d_in[5];
    const float* root2 = (const float*)d_in[6];
    const float* b2    = (const float*)d_in[7];
    float* out = (float*)d_out;

    const int E = in_sizes[1] / 2;
    const int* src = ei;
    const int* dst = ei + E;

    k_zero<<<(N_NODES * H_DIM + 255) / 256, 256>>>();
    k_proj1<<<(N_NODES + 63) / 64, 256>>>(x, W1, root1);
    long long tE = 4LL * E;
    k_edge<<<(int)((tE + 255) / 256), 256>>>(src, dst, E, 0);
    k_combine1<<<(N_NODES * 4 + 255) / 256, 256>>>(b1);
    k_edge<<<(int)((tE + 255) / 256), 256>>>(src, dst, E, 1);
    k_out<<<(N_NODES + 7) / 8, 256>>>(W2, root2, b2, out);
}